// round 13
// baseline (speedup 1.0000x reference)
#include <cuda_runtime.h>
#include <cuda_fp16.h>
#include <float.h>
#include <stdint.h>

// ---------------- problem constants ----------------
#define NTOK   32768
#define DIM    1024
#define NEXP   64
#define NGRP   4
#define GRPSZ  16

// output layout (float32): idx | scores | probs_full | importance | load
#define OFF_IDX   0
#define OFF_SC    (NTOK*2)
#define OFF_PROBS (NTOK*4)
#define OFF_IMP   (OFF_PROBS + NTOK*NEXP)
#define OFF_LOAD  (OFF_IMP + NEXP)

// ---------------- tiling ----------------
#define TILE_M 128
#define NPAD   72            // 64 experts + 4 groups + 4 zero rows
#define KC     64            // K elements per chunk (64 fp16 = 128B row)
#define NCHUNK (DIM/KC)      // 16
#define NTHR   256

#define WSCALE     64.0f
#define INV_WSCALE 0.015625f

// smem (dynamic, bytes): double-buffered, 2 fp16 planes for A and B
#define A_PL    (TILE_M*128)                 // 16384 per plane
#define B_PL    (NPAD*128)                   // 9216 per plane
#define BUF_SZ  (2*A_PL + 2*B_PL)            // 51200 per buffer
#define SM_B_OFF (2*A_PL)                    // B planes after A planes within buffer
#define SM_TOTAL (2*BUF_SZ)                  // 102400

#define LGP 76   // logits/probs staging pitch (floats)

__device__ int g_counts[NEXP];
__device__ __align__(16) __half W_pre[2][NPAD*DIM];   // pre-split scaled W planes

// ---------------- helpers ----------------
__device__ __forceinline__ uint32_t smem_u32(const void* p) {
    return (uint32_t)__cvta_generic_to_shared(p);
}
__device__ __forceinline__ void ldmx4(uint32_t addr, uint32_t* r) {
    asm volatile("ldmatrix.sync.aligned.m8n8.x4.shared.b16 {%0,%1,%2,%3}, [%4];"
                 : "=r"(r[0]), "=r"(r[1]), "=r"(r[2]), "=r"(r[3]) : "r"(addr));
}
__device__ __forceinline__ void ldmx2(uint32_t addr, uint32_t* r) {
    asm volatile("ldmatrix.sync.aligned.m8n8.x2.shared.b16 {%0,%1}, [%2];"
                 : "=r"(r[0]), "=r"(r[1]) : "r"(addr));
}
__device__ __forceinline__ void mma16816(float* d, const uint32_t* a,
                                         uint32_t b0, uint32_t b1) {
    asm volatile("mma.sync.aligned.m16n8k16.row.col.f32.f16.f16.f32 "
                 "{%0,%1,%2,%3}, {%4,%5,%6,%7}, {%8,%9}, {%0,%1,%2,%3};"
                 : "+f"(d[0]), "+f"(d[1]), "+f"(d[2]), "+f"(d[3])
                 : "r"(a[0]), "r"(a[1]), "r"(a[2]), "r"(a[3]), "r"(b0), "r"(b1));
}
__device__ __forceinline__ uint32_t pack2h(float a, float b) {
    __half2 t = __floats2half2_rn(a, b);
    return *reinterpret_cast<uint32_t*>(&t);
}
// fp32x4 -> 2 fp16 planes (hi/mid)
__device__ __forceinline__ void cvt2x4(float4 v, uint2& h, uint2& m) {
    float f[4] = {v.x, v.y, v.z, v.w};
    float fm[4];
#pragma unroll
    for (int i = 0; i < 4; ++i) {
        __half hh = __float2half_rn(f[i]);
        fm[i] = f[i] - __half2float(hh);     // exact in fp32
        f[i]  = __half2float(hh);            // exact
    }
    h = make_uint2(pack2h(f[0], f[1]), pack2h(f[2], f[3]));
    m = make_uint2(pack2h(fm[0], fm[1]), pack2h(fm[2], fm[3]));
}

// ---------------- small kernels ----------------
__global__ void zero_kernel(float* out) {
    int t = threadIdx.x;
    if (t < NEXP) { out[OFF_IMP + t] = 0.0f; g_counts[t] = 0; }
}
__global__ void finalize_kernel(float* out) {
    int t = threadIdx.x;
    if (t < NEXP) out[OFF_LOAD + t] = (float)g_counts[t] * (1.0f / (float)(NTOK * 2));
}
// pre-split W (scaled by 64) into fp16 hi/mid planes
__global__ void prep_kernel(const float* __restrict__ Wg, const float* __restrict__ We) {
    int r = blockIdx.x;
    int t = threadIdx.x;
#pragma unroll
    for (int j = 0; j < 4; ++j) {
        int k = t + j * 256;
        float v = 0.0f;
        if (r < NEXP)          v = We[r * DIM + k];
        else if (r < NEXP + 4) v = Wg[(r - NEXP) * DIM + k];
        v *= WSCALE;
        __half h = __float2half_rn(v);
        float rm = v - __half2float(h);
        W_pre[0][r * DIM + k] = h;
        W_pre[1][r * DIM + k] = __float2half_rn(rm);
    }
}

// ---------------- main kernel ----------------
__global__ __launch_bounds__(NTHR, 2)
void router_mma(const float* __restrict__ xg,
                float* __restrict__ out) {
    extern __shared__ char smem[];
    __shared__ int cnt_s[NEXP];
    const uint32_t sb = smem_u32(smem);
    const int tid = threadIdx.x;
    const int w   = tid >> 5;
    const int L   = tid & 31;
    const int tok0 = blockIdx.x * TILE_M;

    if (tid < NEXP) cnt_s[tid] = 0;

    float acc[9][4];
#pragma unroll
    for (int t = 0; t < 9; ++t)
#pragma unroll
        for (int i = 0; i < 4; ++i) acc[t][i] = 0.0f;

    // per-thread A-store addressing (same every chunk)
    const int aRow = tid >> 1;                 // rows 0..127, 2 threads/row
    const int aC4h = (tid & 1) * 8;            // c4 base: 0 or 8
    // ldmatrix A lane addressing
    const int rowA  = 16 * w + (L & 15);
    const uint32_t aRowOff = rowA * 128;
    const int sA    = rowA & 7;
    const int aHi   = L >> 4;
    // ldmatrix B pair addressing
    const int bSel  = (L >> 4) & 1;
    const int bKbit = (L >> 3) & 1;
    const int bR7   = L & 7;

    float4 xv[8];

    // ---- prologue: load + convert + store chunk 0 into buffer 0 ----
#pragma unroll
    for (int j = 0; j < 8; ++j) {
        int idx = tid + j * NTHR;
        int row = idx >> 4, c4 = idx & 15;
        xv[j] = *(const float4*)(xg + (size_t)(tok0 + row) * DIM + c4 * 4);
    }
#pragma unroll
    for (int j = 0; j < 8; ++j) {
        int idx = tid + j * NTHR;
        int row = idx >> 4, c4 = idx & 15;
        uint2 h, m;
        cvt2x4(xv[j], h, m);
        uint32_t off = row * 128 + (((c4 >> 1) ^ (row & 7)) << 4) + ((c4 & 1) << 3);
        *(uint2*)(smem + 0 * A_PL + off) = h;
        *(uint2*)(smem + 1 * A_PL + off) = m;
    }
    for (int i = tid; i < NPAD * 8; i += NTHR) {
        int r = i >> 3, c8 = i & 7;
        uint32_t off = r * 128 + ((c8 ^ (r & 7)) << 4);
        *(uint4*)(smem + SM_B_OFF + 0 * B_PL + off) = *(const uint4*)&W_pre[0][r * DIM + c8 * 8];
        *(uint4*)(smem + SM_B_OFF + 1 * B_PL + off) = *(const uint4*)&W_pre[1][r * DIM + c8 * 8];
    }
    __syncthreads();

    // ---- pipelined main loop: one sync per chunk ----
    for (int c = 0; c < NCHUNK; ++c) {
        const uint32_t cb = (uint32_t)(c & 1) * BUF_SZ;          // current buffer
        const uint32_t nb = (uint32_t)((c + 1) & 1) * BUF_SZ;    // next buffer
        const int k1 = (c + 1) * KC;

        // prefetch next chunk's x into registers (hidden under MMA)
        if (c + 1 < NCHUNK) {
#pragma unroll
            for (int j = 0; j < 8; ++j) {
                int idx = tid + j * NTHR;
                int row = idx >> 4, c4 = idx & 15;
                xv[j] = *(const float4*)(xg + (size_t)(tok0 + row) * DIM + k1 + c4 * 4);
            }
        }

        // MMA on current buffer (tensor pipe) — 4 k-slabs of 16
#pragma unroll
        for (int ks = 0; ks < 4; ++ks) {
            uint32_t Ah[4], Am[4];
            {
                uint32_t aoff = cb + aRowOff + ((((ks * 2) + aHi) ^ sA) << 4);
                ldmx4(sb + 0 * A_PL + aoff, Ah);
                ldmx4(sb + 1 * A_PL + aoff, Am);
            }
#pragma unroll
            for (int j = 0; j < 4; ++j) {
                uint32_t Bh[4], Bm[4];
                int brow = (2 * j + bSel) * 8 + bR7;
                uint32_t boff = cb + SM_B_OFF + brow * 128 + ((((ks * 2) + bKbit) ^ (brow & 7)) << 4);
                ldmx4(sb + 0 * B_PL + boff, Bh);
                ldmx4(sb + 1 * B_PL + boff, Bm);
                mma16816(acc[2*j],   Ah, Bh[0], Bh[1]);
                mma16816(acc[2*j],   Ah, Bm[0], Bm[1]);
                mma16816(acc[2*j],   Am, Bh[0], Bh[1]);
                mma16816(acc[2*j+1], Ah, Bh[2], Bh[3]);
                mma16816(acc[2*j+1], Ah, Bm[2], Bm[3]);
                mma16816(acc[2*j+1], Am, Bh[2], Bh[3]);
            }
            {   // last n-tile (cols 64..71)
                uint32_t Bh[2], Bm[2];
                int brow = 64 + bR7;
                uint32_t boff = cb + SM_B_OFF + brow * 128 + ((((ks * 2) + bKbit) ^ (brow & 7)) << 4);
                ldmx2(sb + 0 * B_PL + boff, Bh);
                ldmx2(sb + 1 * B_PL + boff, Bm);
                mma16816(acc[8], Ah, Bh[0], Bh[1]);
                mma16816(acc[8], Ah, Bm[0], Bm[1]);
                mma16816(acc[8], Am, Bh[0], Bh[1]);
            }
        }

        // convert + store next chunk into the other buffer (FMA/LSU pipes,
        // overlaps the tensor-pipe MMAs above at issue level)
        if (c + 1 < NCHUNK) {
#pragma unroll
            for (int j = 0; j < 8; ++j) {
                int idx = tid + j * NTHR;
                int row = idx >> 4, c4 = idx & 15;
                uint2 h, m;
                cvt2x4(xv[j], h, m);
                uint32_t off = nb + row * 128 + (((c4 >> 1) ^ (row & 7)) << 4) + ((c4 & 1) << 3);
                *(uint2*)(smem + 0 * A_PL + off) = h;
                *(uint2*)(smem + 1 * A_PL + off) = m;
            }
            for (int i = tid; i < NPAD * 8; i += NTHR) {
                int r = i >> 3, c8 = i & 7;
                uint32_t off = nb + SM_B_OFF + r * 128 + ((c8 ^ (r & 7)) << 4);
                *(uint4*)(smem + 0 * B_PL + off) = *(const uint4*)&W_pre[0][r * DIM + k1 + c8 * 8];
                *(uint4*)(smem + 1 * B_PL + off) = *(const uint4*)&W_pre[1][r * DIM + k1 + c8 * 8];
            }
        }
        __syncthreads();
    }

    // ---- epilogue ----
    float* lg = (float*)smem;   // [128][LGP]
    {
        int r0 = 16 * w + (L >> 2);
        int r1 = r0 + 8;
        int cbx = 2 * (L & 3);
#pragma unroll
        for (int t = 0; t < 9; ++t) {
            *(float2*)&lg[r0 * LGP + t * 8 + cbx] = make_float2(acc[t][0], acc[t][1]);
            *(float2*)&lg[r1 * LGP + t * 8 + cbx] = make_float2(acc[t][2], acc[t][3]);
        }
    }
    __syncthreads();

    if (tid < TILE_M) {   // one thread per token
        float d[68];
#pragma unroll
        for (int e = 0; e < 68; ++e) d[e] = lg[tid * LGP + e] * INV_WSCALE;

        // group argmax (first-max tie-break == jnp.argmax)
        int g = 0; float gbest = d[NEXP + 0];
#pragma unroll
        for (int j = 1; j < NGRP; ++j)
            if (d[NEXP + j] > gbest) { gbest = d[NEXP + j]; g = j; }
        const int ebase = g * GRPSZ;

        // in-group top-2 (lower index wins ties, matches jax top_k)
        float v1 = -FLT_MAX, v2 = -FLT_MAX; int i1 = 0, i2 = 0;
#pragma unroll
        for (int e = 0; e < GRPSZ; ++e) {
            float v = d[ebase + e];
            if (v > v1) { v2 = v1; i2 = i1; v1 = v; i1 = e; }
            else if (v > v2) { v2 = v; i2 = e; }
        }
        // masked softmax: out-of-group exactly 0
        float ex[GRPSZ], denom = 0.f;
#pragma unroll
        for (int e = 0; e < GRPSZ; ++e) { ex[e] = __expf(d[ebase + e] - v1); denom += ex[e]; }
        float inv = 1.f / denom;

        float e2v = __expf(v2 - v1);
        float s1 = 1.f / (1.f + e2v);
        float s2 = e2v * s1;
        int tok = tok0 + tid;
        out[OFF_IDX + tok * 2 + 0] = (float)(ebase + i1);
        out[OFF_IDX + tok * 2 + 1] = (float)(ebase + i2);
        out[OFF_SC  + tok * 2 + 0] = s1;
        out[OFF_SC  + tok * 2 + 1] = s2;
        atomicAdd(&cnt_s[ebase + i1], 1);
        atomicAdd(&cnt_s[ebase + i2], 1);

        // overwrite row with probs
#pragma unroll
        for (int q = 0; q < 16; ++q) {
            float4 pv;
            float* pf = (float*)&pv;
#pragma unroll
            for (int u = 0; u < 4; ++u) {
                int e = q * 4 + u;
                pf[u] = (e >= ebase && e < ebase + GRPSZ) ? ex[e - ebase] * inv : 0.0f;
            }
            *(float4*)&lg[tid * LGP + q * 4] = pv;
        }
    }
    __syncthreads();

    // coalesced probs store
    for (int i = tid; i < TILE_M * 16; i += NTHR) {
        int t = i >> 4, q = i & 15;
        float4 v = *(const float4*)&lg[t * LGP + q * 4];
        *(float4*)(out + OFF_PROBS + (size_t)(tok0 + t) * NEXP + q * 4) = v;
    }
    // importance + counts
    if (tid < NEXP) {
        float s = 0.f;
        for (int t = 0; t < TILE_M; ++t) s += lg[t * LGP + tid];
        atomicAdd(&out[OFF_IMP + tid], s * (1.0f / (float)NTOK));
        int cc = cnt_s[tid];
        if (cc) atomicAdd(&g_counts[tid], cc);
    }
}

// ---------------- launch ----------------
extern "C" void kernel_launch(void* const* d_in, const int* in_sizes, int n_in,
                              void* d_out, int out_size) {
    const float *x = nullptr, *Wg = nullptr, *We = nullptr;
    for (int i = 0; i < n_in; ++i) {
        if (in_sizes[i] == NTOK * DIM)      x  = (const float*)d_in[i];
        else if (in_sizes[i] == NGRP * DIM) Wg = (const float*)d_in[i];
        else if (in_sizes[i] == NEXP * DIM) We = (const float*)d_in[i];
    }
    float* out = (float*)d_out;
    cudaFuncSetAttribute(router_mma, cudaFuncAttributeMaxDynamicSharedMemorySize, SM_TOTAL);
    zero_kernel<<<1, 64>>>(out);
    prep_kernel<<<NPAD, 256>>>(Wg, We);
    router_mma<<<NTOK / TILE_M, NTHR, SM_TOTAL>>>(x, out);
    finalize_kernel<<<1, 64>>>(out);
}

// round 15
// speedup vs baseline: 1.1854x; 1.1854x over previous
#include <cuda_runtime.h>
#include <cuda_fp16.h>
#include <float.h>
#include <stdint.h>

// ---------------- problem constants ----------------
#define NTOK   32768
#define DIM    1024
#define NEXP   64
#define NGRP   4
#define GRPSZ  16

// output layout (float32): idx | scores | probs_full | importance | load
#define OFF_IDX   0
#define OFF_SC    (NTOK*2)
#define OFF_PROBS (NTOK*4)
#define OFF_IMP   (OFF_PROBS + NTOK*NEXP)
#define OFF_LOAD  (OFF_IMP + NEXP)

// ---------------- tiling ----------------
#define TILE_M 128
#define NPAD   72            // 64 experts + 4 groups + 4 zero rows
#define KC     64            // K elements per chunk (64 fp16 = 128B row)
#define NCHUNK (DIM/KC)      // 16
#define NTHR   256

#define WSCALE     64.0f
#define INV_WSCALE 0.015625f

// smem (dynamic, bytes): 2 fp16 planes for A and B, 128B rows, swizzled
#define A_PL   (TILE_M*128)          // 16384 per plane
#define SM_A   0
#define B_PL   (NPAD*128)            // 9216 per plane
#define SM_B   (2*A_PL)              // 32768
#define SM_TOTAL (SM_B + 2*B_PL)     // 51200

#define LGP 76   // logits/probs staging pitch (floats)

__device__ int g_counts[NEXP];
__device__ __align__(16) __half W_pre[2][NPAD*DIM];   // pre-split scaled W planes

// ---------------- helpers ----------------
__device__ __forceinline__ uint32_t smem_u32(const void* p) {
    return (uint32_t)__cvta_generic_to_shared(p);
}
__device__ __forceinline__ void ldmx4(uint32_t addr, uint32_t* r) {
    asm volatile("ldmatrix.sync.aligned.m8n8.x4.shared.b16 {%0,%1,%2,%3}, [%4];"
                 : "=r"(r[0]), "=r"(r[1]), "=r"(r[2]), "=r"(r[3]) : "r"(addr));
}
__device__ __forceinline__ void ldmx2(uint32_t addr, uint32_t* r) {
    asm volatile("ldmatrix.sync.aligned.m8n8.x2.shared.b16 {%0,%1}, [%2];"
                 : "=r"(r[0]), "=r"(r[1]) : "r"(addr));
}
__device__ __forceinline__ void mma16816(float* d, const uint32_t* a,
                                         uint32_t b0, uint32_t b1) {
    asm volatile("mma.sync.aligned.m16n8k16.row.col.f32.f16.f16.f32 "
                 "{%0,%1,%2,%3}, {%4,%5,%6,%7}, {%8,%9}, {%0,%1,%2,%3};"
                 : "+f"(d[0]), "+f"(d[1]), "+f"(d[2]), "+f"(d[3])
                 : "r"(a[0]), "r"(a[1]), "r"(a[2]), "r"(a[3]), "r"(b0), "r"(b1));
}
__device__ __forceinline__ uint32_t pack2h(float a, float b) {
    __half2 t = __floats2half2_rn(a, b);
    return *reinterpret_cast<uint32_t*>(&t);
}
// fp32x4 -> 2 fp16 planes (hi/mid)
__device__ __forceinline__ void cvt2x4(float4 v, uint2& h, uint2& m) {
    float f[4] = {v.x, v.y, v.z, v.w};
    float fm[4];
#pragma unroll
    for (int i = 0; i < 4; ++i) {
        __half hh = __float2half_rn(f[i]);
        fm[i] = f[i] - __half2float(hh);     // exact in fp32
        f[i]  = __half2float(hh);            // exact
    }
    h = make_uint2(pack2h(f[0], f[1]), pack2h(f[2], f[3]));
    m = make_uint2(pack2h(fm[0], fm[1]), pack2h(fm[2], fm[3]));
}

// ---------------- small kernels ----------------
// blocks 0..NPAD-1: pre-split W (scaled by 64) into fp16 hi/mid planes.
// block 0 additionally zeroes importance + counts.
__global__ void prep_kernel(const float* __restrict__ Wg, const float* __restrict__ We,
                            float* __restrict__ out) {
    int r = blockIdx.x;
    int t = threadIdx.x;
    if (r == 0 && t < NEXP) { out[OFF_IMP + t] = 0.0f; g_counts[t] = 0; }
#pragma unroll
    for (int j = 0; j < 4; ++j) {
        int k = t + j * 256;
        float v = 0.0f;
        if (r < NEXP)          v = We[r * DIM + k];
        else if (r < NEXP + 4) v = Wg[(r - NEXP) * DIM + k];
        v *= WSCALE;
        __half h = __float2half_rn(v);
        float rm = v - __half2float(h);
        W_pre[0][r * DIM + k] = h;
        W_pre[1][r * DIM + k] = __float2half_rn(rm);
    }
}
__global__ void finalize_kernel(float* out) {
    int t = threadIdx.x;
    if (t < NEXP) out[OFF_LOAD + t] = (float)g_counts[t] * (1.0f / (float)(NTOK * 2));
}

// ---------------- main kernel ----------------
__global__ __launch_bounds__(NTHR, 2)
void router_mma(const float* __restrict__ xg,
                float* __restrict__ out) {
    extern __shared__ char smem[];
    __shared__ int cnt_s[NEXP];
    const uint32_t sb = smem_u32(smem);
    const int tid = threadIdx.x;
    const int w   = tid >> 5;
    const int L   = tid & 31;
    const int tok0 = blockIdx.x * TILE_M;

    if (tid < NEXP) cnt_s[tid] = 0;

    float acc[9][4];
#pragma unroll
    for (int t = 0; t < 9; ++t)
#pragma unroll
        for (int i = 0; i < 4; ++i) acc[t][i] = 0.0f;

    // ldmatrix A lane addressing: row = 16w + (L&15), chunk = ks*2 + (L>>4)
    const int rowA  = 16 * w + (L & 15);
    const uint32_t aRowOff = rowA * 128;
    const int sA    = rowA & 7;
    const int aHi   = L >> 4;
    // ldmatrix B pair addressing
    const int bSel  = (L >> 4) & 1;
    const int bKbit = (L >> 3) & 1;
    const int bR7   = L & 7;

    for (int c = 0; c < NCHUNK; ++c) {
        const int k0 = c * KC;
        // prefetch x tile [128 x 64] fp32 (coalesced float4)
        float4 xv[8];
#pragma unroll
        for (int j = 0; j < 8; ++j) {
            int idx = tid + j * NTHR;
            int row = idx >> 4, c4 = idx & 15;
            xv[j] = *(const float4*)(xg + (size_t)(tok0 + row) * DIM + k0 + c4 * 4);
        }
        __syncthreads();   // previous chunk's mma reads complete

        // A planes: convert + swizzled store (16B-chunk XOR by row&7)
#pragma unroll
        for (int j = 0; j < 8; ++j) {
            int idx = tid + j * NTHR;
            int row = idx >> 4, c4 = idx & 15;
            uint2 h, m;
            cvt2x4(xv[j], h, m);
            uint32_t off = row * 128 + (((c4 >> 1) ^ (row & 7)) << 4) + ((c4 & 1) << 3);
            *(uint2*)(smem + SM_A + 0 * A_PL + off) = h;
            *(uint2*)(smem + SM_A + 1 * A_PL + off) = m;
        }
        // B planes [72 x 64]: copy pre-split fp16 planes (16B per row-chunk)
        for (int i = tid; i < NPAD * 8; i += NTHR) {
            int r = i >> 3, c8 = i & 7;
            uint32_t off = r * 128 + ((c8 ^ (r & 7)) << 4);
            *(uint4*)(smem + SM_B + 0 * B_PL + off) =
                *(const uint4*)&W_pre[0][r * DIM + k0 + c8 * 8];
            *(uint4*)(smem + SM_B + 1 * B_PL + off) =
                *(const uint4*)&W_pre[1][r * DIM + k0 + c8 * 8];
        }
        __syncthreads();

        // mma over 4 k-slabs of 16 — interleaved accumulators (dep distance >= 2)
#pragma unroll
        for (int ks = 0; ks < 4; ++ks) {
            uint32_t Ah[4], Am[4];
            {
                uint32_t aoff = aRowOff + ((((ks * 2) + aHi) ^ sA) << 4);
                ldmx4(sb + SM_A + 0 * A_PL + aoff, Ah);
                ldmx4(sb + SM_A + 1 * A_PL + aoff, Am);
            }
#pragma unroll
            for (int j = 0; j < 3; ++j) {
                uint32_t Bh[4], Bm[4];
                int brow = (2 * j + bSel) * 8 + bR7;
                uint32_t boff = brow * 128 + ((((ks * 2) + bKbit) ^ (brow & 7)) << 4);
                ldmx4(sb + SM_B + 0 * B_PL + boff, Bh);
                ldmx4(sb + SM_B + 1 * B_PL + boff, Bm);
                // per-acc order hh,hm,mh preserved; interleaved across the pair
                mma16816(acc[2*j],   Ah, Bh[0], Bh[1]);
                mma16816(acc[2*j+1], Ah, Bh[2], Bh[3]);
                mma16816(acc[2*j],   Ah, Bm[0], Bm[1]);
                mma16816(acc[2*j+1], Ah, Bm[2], Bm[3]);
                mma16816(acc[2*j],   Am, Bh[0], Bh[1]);
                mma16816(acc[2*j+1], Am, Bh[2], Bh[3]);
            }
            {   // j = 3 fused with tail tile (cols 64..71): dep distance 3
                uint32_t Bh[4], Bm[4], Bh8[2], Bm8[2];
                int brow = (6 + bSel) * 8 + bR7;
                uint32_t boff = brow * 128 + ((((ks * 2) + bKbit) ^ (brow & 7)) << 4);
                ldmx4(sb + SM_B + 0 * B_PL + boff, Bh);
                ldmx4(sb + SM_B + 1 * B_PL + boff, Bm);
                int brow8 = 64 + bR7;
                uint32_t boff8 = brow8 * 128 + ((((ks * 2) + bKbit) ^ (brow8 & 7)) << 4);
                ldmx2(sb + SM_B + 0 * B_PL + boff8, Bh8);
                ldmx2(sb + SM_B + 1 * B_PL + boff8, Bm8);
                mma16816(acc[6], Ah, Bh[0], Bh[1]);
                mma16816(acc[7], Ah, Bh[2], Bh[3]);
                mma16816(acc[8], Ah, Bh8[0], Bh8[1]);
                mma16816(acc[6], Ah, Bm[0], Bm[1]);
                mma16816(acc[7], Ah, Bm[2], Bm[3]);
                mma16816(acc[8], Ah, Bm8[0], Bm8[1]);
                mma16816(acc[6], Am, Bh[0], Bh[1]);
                mma16816(acc[7], Am, Bh[2], Bh[3]);
                mma16816(acc[8], Am, Bh8[0], Bh8[1]);
            }
        }
    }
    __syncthreads();   // all mma done; smem free for logits staging

    float* lg = (float*)smem;   // [128][LGP]
    {
        int r0 = 16 * w + (L >> 2);
        int r1 = r0 + 8;
        int cb = 2 * (L & 3);
#pragma unroll
        for (int t = 0; t < 9; ++t) {
            *(float2*)&lg[r0 * LGP + t * 8 + cb] = make_float2(acc[t][0], acc[t][1]);
            *(float2*)&lg[r1 * LGP + t * 8 + cb] = make_float2(acc[t][2], acc[t][3]);
        }
    }
    __syncthreads();

    if (tid < TILE_M) {   // one thread per token
        float d[68];
#pragma unroll
        for (int e = 0; e < 68; ++e) d[e] = lg[tid * LGP + e] * INV_WSCALE;

        // group argmax (first-max tie-break == jnp.argmax)
        int g = 0; float gbest = d[NEXP + 0];
#pragma unroll
        for (int j = 1; j < NGRP; ++j)
            if (d[NEXP + j] > gbest) { gbest = d[NEXP + j]; g = j; }
        const int ebase = g * GRPSZ;

        // in-group top-2 (lower index wins ties, matches jax top_k)
        float v1 = -FLT_MAX, v2 = -FLT_MAX; int i1 = 0, i2 = 0;
#pragma unroll
        for (int e = 0; e < GRPSZ; ++e) {
            float v = d[ebase + e];
            if (v > v1) { v2 = v1; i2 = i1; v1 = v; i1 = e; }
            else if (v > v2) { v2 = v; i2 = e; }
        }
        // masked softmax: out-of-group exactly 0
        float ex[GRPSZ], denom = 0.f;
#pragma unroll
        for (int e = 0; e < GRPSZ; ++e) { ex[e] = __expf(d[ebase + e] - v1); denom += ex[e]; }
        float inv = 1.f / denom;

        float e2v = __expf(v2 - v1);
        float s1 = 1.f / (1.f + e2v);
        float s2 = e2v * s1;
        int tok = tok0 + tid;
        out[OFF_IDX + tok * 2 + 0] = (float)(ebase + i1);
        out[OFF_IDX + tok * 2 + 1] = (float)(ebase + i2);
        out[OFF_SC  + tok * 2 + 0] = s1;
        out[OFF_SC  + tok * 2 + 1] = s2;
        atomicAdd(&cnt_s[ebase + i1], 1);
        atomicAdd(&cnt_s[ebase + i2], 1);

        // overwrite row with probs
#pragma unroll
        for (int q = 0; q < 16; ++q) {
            float4 pv;
            float* pf = (float*)&pv;
#pragma unroll
            for (int u = 0; u < 4; ++u) {
                int e = q * 4 + u;
                pf[u] = (e >= ebase && e < ebase + GRPSZ) ? ex[e - ebase] * inv : 0.0f;
            }
            *(float4*)&lg[tid * LGP + q * 4] = pv;
        }
    }
    __syncthreads();

    // coalesced probs store
    for (int i = tid; i < TILE_M * 16; i += NTHR) {
        int t = i >> 4, q = i & 15;
        float4 v = *(const float4*)&lg[t * LGP + q * 4];
        *(float4*)(out + OFF_PROBS + (size_t)(tok0 + t) * NEXP + q * 4) = v;
    }
    // importance + counts
    if (tid < NEXP) {
        float s = 0.f;
        for (int t = 0; t < TILE_M; ++t) s += lg[t * LGP + tid];
        atomicAdd(&out[OFF_IMP + tid], s * (1.0f / (float)NTOK));
        int cc = cnt_s[tid];
        if (cc) atomicAdd(&g_counts[tid], cc);
    }
}

// ---------------- launch ----------------
extern "C" void kernel_launch(void* const* d_in, const int* in_sizes, int n_in,
                              void* d_out, int out_size) {
    const float *x = nullptr, *Wg = nullptr, *We = nullptr;
    for (int i = 0; i < n_in; ++i) {
        if (in_sizes[i] == NTOK * DIM)      x  = (const float*)d_in[i];
        else if (in_sizes[i] == NGRP * DIM) Wg = (const float*)d_in[i];
        else if (in_sizes[i] == NEXP * DIM) We = (const float*)d_in[i];
    }
    float* out = (float*)d_out;
    cudaFuncSetAttribute(router_mma, cudaFuncAttributeMaxDynamicSharedMemorySize, SM_TOTAL);
    prep_kernel<<<NPAD, 256>>>(Wg, We, out);
    router_mma<<<NTOK / TILE_M, NTHR, SM_TOTAL>>>(x, out);
    finalize_kernel<<<1, 64>>>(out);
}